// round 11
// baseline (speedup 1.0000x reference)
#include <cuda_runtime.h>
#include <cuda_fp16.h>

// Problem shapes (fixed by the dataset)
#define BSZ  8
#define ENL  512   // encoder length
#define DEL  64    // decoder length
#define EDIM 512   // embedding
#define UDIM 512   // units
#define TDIM 100   // topics
#define STRIP 8    // strip depth in fused kernel

// Scratch (no cudaMalloc allowed)
__device__ __half g_aeT[BSZ * UDIM * ENL];  // att_en transposed: [b][u][i] (fp16, 4 MB)
__device__ float  g_c  [BSZ * DEL * UDIM];  // att_de + topic bias: [b][j][u] (1 MB)

typedef unsigned long long ull;

__device__ __forceinline__ ull pack2(float x, float y) {
    ull r; asm("mov.b64 %0, {%1, %2};" : "=l"(r) : "f"(x), "f"(y)); return r;
}
__device__ __forceinline__ void unpack2(ull p, float& x, float& y) {
    asm("mov.b64 {%0, %1}, %2;" : "=f"(x), "=f"(y) : "l"(p));
}
__device__ __forceinline__ ull fma2(ull a, ull b, ull c) {
    ull d; asm("fma.rn.f32x2 %0, %1, %2, %3;" : "=l"(d) : "l"(a), "l"(b), "l"(c));
    return d;
}
__device__ __forceinline__ unsigned cvt_f16x2(float lo, float hi) {
    unsigned p;
    asm("cvt.rn.f16x2.f32 %0, %1, %2;" : "=r"(p) : "f"(hi), "f"(lo));
    return p;
}
// Two tanhs in one MUFU op: returns (tanh(s0), tanh(s1)) in fp32.
__device__ __forceinline__ float2 tanh2_f16(float s0, float s1) {
    unsigned p = cvt_f16x2(s0, s1), q;
    asm("tanh.approx.f16x2 %0, %1;" : "=r"(q) : "r"(p));
    __half2 h = *reinterpret_cast<__half2*>(&q);
    return __half22float2(h);   // (lo, hi)
}

// ---------------------------------------------------------------------------
// Kernel 1: g_aeT[b][u][i] = (half) sum_e en[b][i][e] * w_en[e][u]
// 64(i) x 128(u) tile, BK=16, 256 threads, 8(u)x4(i) microtile, f32x2 FMAs.
// A read as NATIVE f32 pairs — zero movs. B splatted with 4 movs per k-step.
// ---------------------------------------------------------------------------
__global__ void __launch_bounds__(256, 2) k_gemm_aeT(
    const float* __restrict__ en, const float* __restrict__ w_en)
{
    const int b  = blockIdx.z;
    const int u0 = blockIdx.y * 128;
    const int i0 = blockIdx.x * 64;

    __shared__ float As[2][16][128];  // [e][u]
    __shared__ float Bs[2][16][68];   // [e][i] (padded)

    const int tid = threadIdx.x;
    const int tx = tid & 15;
    const int ty = tid >> 4;

    const int ua = tid & 127;
    const int ea = tid >> 7;
    const int eb = tid & 15;
    const int ib = tid >> 4;

    const float* pa = w_en + (size_t)ea * UDIM + u0 + ua;
    const float* pb = en + (size_t)b * ENL * EDIM + (size_t)(i0 + ib) * EDIM + eb;

    ull acc[4][4] = {};   // [u-pair][i]

    #pragma unroll
    for (int p = 0; p < 8; p++)
        As[0][ea + 2 * p][ua] = pa[(size_t)(2 * p) * UDIM];
    #pragma unroll
    for (int p = 0; p < 4; p++)
        Bs[0][eb][ib + 16 * p] = pb[(size_t)(16 * p) * EDIM];
    __syncthreads();

    int s = 0;
    for (int t = 0; t < 32; t++) {
        float ra[8], rb[4];
        if (t < 31) {
            const float* qa = pa + (size_t)(t + 1) * 16 * UDIM;
            const float* qb = pb + (t + 1) * 16;
            #pragma unroll
            for (int p = 0; p < 8; p++) ra[p] = qa[(size_t)(2 * p) * UDIM];
            #pragma unroll
            for (int p = 0; p < 4; p++) rb[p] = qb[(size_t)(16 * p) * EDIM];
        }
        #pragma unroll
        for (int k = 0; k < 16; k++) {
            const ulonglong2 A03 = *(const ulonglong2*)&As[s][k][ty * 8];
            const ulonglong2 A47 = *(const ulonglong2*)&As[s][k][ty * 8 + 4];
            const float4 bv = *(const float4*)&Bs[s][k][tx * 4];
            const ull b0 = pack2(bv.x, bv.x), b1 = pack2(bv.y, bv.y);
            const ull b2 = pack2(bv.z, bv.z), b3 = pack2(bv.w, bv.w);
            acc[0][0]=fma2(A03.x,b0,acc[0][0]); acc[0][1]=fma2(A03.x,b1,acc[0][1]);
            acc[0][2]=fma2(A03.x,b2,acc[0][2]); acc[0][3]=fma2(A03.x,b3,acc[0][3]);
            acc[1][0]=fma2(A03.y,b0,acc[1][0]); acc[1][1]=fma2(A03.y,b1,acc[1][1]);
            acc[1][2]=fma2(A03.y,b2,acc[1][2]); acc[1][3]=fma2(A03.y,b3,acc[1][3]);
            acc[2][0]=fma2(A47.x,b0,acc[2][0]); acc[2][1]=fma2(A47.x,b1,acc[2][1]);
            acc[2][2]=fma2(A47.x,b2,acc[2][2]); acc[2][3]=fma2(A47.x,b3,acc[2][3]);
            acc[3][0]=fma2(A47.y,b0,acc[3][0]); acc[3][1]=fma2(A47.y,b1,acc[3][1]);
            acc[3][2]=fma2(A47.y,b2,acc[3][2]); acc[3][3]=fma2(A47.y,b3,acc[3][3]);
        }
        if (t < 31) {
            #pragma unroll
            for (int p = 0; p < 8; p++) As[s ^ 1][ea + 2 * p][ua] = ra[p];
            #pragma unroll
            for (int p = 0; p < 4; p++) Bs[s ^ 1][eb][ib + 16 * p] = rb[p];
        }
        __syncthreads();
        s ^= 1;
    }

    float f[8][4];
    #pragma unroll
    for (int up = 0; up < 4; up++)
        #pragma unroll
        for (int i = 0; i < 4; i++)
            unpack2(acc[up][i], f[2 * up][i], f[2 * up + 1][i]);

    __half* outp = g_aeT + (size_t)b * UDIM * ENL
                 + (size_t)(u0 + ty * 8) * ENL + i0 + tx * 4;
    #pragma unroll
    for (int q = 0; q < 8; q++) {
        uint2 hv = make_uint2(cvt_f16x2(f[q][0], f[q][1]),
                              cvt_f16x2(f[q][2], f[q][3]));
        *(uint2*)(outp + (size_t)q * ENL) = hv;
    }
}

// ---------------------------------------------------------------------------
// Kernel 2: g_c[b][j][u] = sum_e de[b][j][e] * w_de[e][u] + tw[b][u]
// ---------------------------------------------------------------------------
__global__ void __launch_bounds__(256) k_c(
    const float* __restrict__ de, const float* __restrict__ w_de,
    const float* __restrict__ topics, const float* __restrict__ wt)
{
    const int b  = blockIdx.y;
    const int u0 = blockIdx.x * 64;
    __shared__ float As[16][68];
    __shared__ float Bs[16][68];
    __shared__ float tws[64];
    const float* deb = de + (size_t)b * DEL * EDIM;
    const int tid = threadIdx.x;
    const int tj = tid & 15;
    const int tu = tid >> 4;
    ull acc2[4][2] = {};

    if (tid < 64) {
        float acc = 0.f;
        const float* wr = wt + (size_t)(u0 + tid) * TDIM;
        const float* tp = topics + b * TDIM;
        #pragma unroll 4
        for (int t = 0; t < TDIM; t++) acc = fmaf(tp[t], wr[t], acc);
        tws[tid] = acc;
    }

    for (int e0 = 0; e0 < EDIM; e0 += 16) {
        #pragma unroll
        for (int r = 0; r < 4; r++) {
            int l = tid + 256 * r;
            int e = l & 15, j = l >> 4;
            As[e][j] = deb[(size_t)j * EDIM + e0 + e];
        }
        #pragma unroll
        for (int r = 0; r < 4; r++) {
            int l = tid + 256 * r;
            int e = l >> 6, uu = l & 63;
            Bs[e][uu] = w_de[(size_t)(e0 + e) * UDIM + u0 + uu];
        }
        __syncthreads();
        #pragma unroll
        for (int k = 0; k < 16; k++) {
            const float4 av = *(const float4*)&As[k][tj * 4];
            const ull b01 = *(const ull*)&Bs[k][tu * 4];
            const ull b23 = *(const ull*)&Bs[k][tu * 4 + 2];
            ull pa0 = pack2(av.x, av.x), pa1 = pack2(av.y, av.y);
            ull pa2 = pack2(av.z, av.z), pa3 = pack2(av.w, av.w);
            acc2[0][0] = fma2(pa0, b01, acc2[0][0]); acc2[0][1] = fma2(pa0, b23, acc2[0][1]);
            acc2[1][0] = fma2(pa1, b01, acc2[1][0]); acc2[1][1] = fma2(pa1, b23, acc2[1][1]);
            acc2[2][0] = fma2(pa2, b01, acc2[2][0]); acc2[2][1] = fma2(pa2, b23, acc2[2][1]);
            acc2[3][0] = fma2(pa3, b01, acc2[3][0]); acc2[3][1] = fma2(pa3, b23, acc2[3][1]);
        }
        __syncthreads();
    }
    #pragma unroll
    for (int r = 0; r < 4; r++) {
        float2 v01, v23;
        unpack2(acc2[r][0], v01.x, v01.y);
        unpack2(acc2[r][1], v23.x, v23.y);
        int j = tj * 4 + r;
        float* row = g_c + ((size_t)b * DEL + j) * UDIM + u0 + tu * 4;
        row[0] = v01.x + tws[tu * 4 + 0];
        row[1] = v01.y + tws[tu * 4 + 1];
        row[2] = v23.x + tws[tu * 4 + 2];
        row[3] = v23.y + tws[tu * 4 + 3];
    }
}

// ---------------------------------------------------------------------------
// Kernel 3 (fused attention): block = (b, j0..j0+3), 1024 threads.
// Two 512-thread halves, each owns a j-pair; both halves share ae/en lines.
// aeT is fp16 -> half the L2 bytes in phase 1.
// ---------------------------------------------------------------------------
__global__ void __launch_bounds__(1024, 1) k_attn(
    const float* __restrict__ en, const float* __restrict__ de,
    const float* __restrict__ nu, float* __restrict__ out)
{
    const int b    = blockIdx.y;
    const int j0   = blockIdx.x * 4;
    const int tid  = threadIdx.x;
    const int half = tid >> 9;          // 0 or 1 -> j-pair
    const int t    = tid & 511;         // i (phase 1) / e (phase 2)

    __shared__ float4 css[2][UDIM];     // [half][u] = (c[jA][u], c[jB][u], nu[u], 0)
    __shared__ float2 red2[2][16];
    __shared__ float2 alph[2][ENL];     // [half][i] = (alpha_jA, alpha_jB)

    const float* cb = g_c + ((size_t)b * DEL + j0 + 2 * half) * UDIM;
    css[half][t] = make_float4(cb[t], cb[UDIM + t], nu[t], 0.f);
    __syncthreads();

    // Phase 1: mu for i = t, own j-pair. Pipelined strips of fp16 loads.
    const __half* ae = g_aeT + (size_t)b * UDIM * ENL + t;
    float m0 = 0.f, m1 = 0.f;
    {
        __half bufA[STRIP], bufB[STRIP];
        #pragma unroll
        for (int k = 0; k < STRIP; k++)
            bufA[k] = __ldg(ae + (size_t)k * ENL);

        #pragma unroll 1
        for (int u0 = 0; u0 < UDIM; u0 += 2 * STRIP) {
            #pragma unroll
            for (int k = 0; k < STRIP; k++)
                bufB[k] = __ldg(ae + (size_t)(u0 + STRIP + k) * ENL);
            #pragma unroll
            for (int k = 0; k < STRIP; k++) {
                float4 c4 = css[half][u0 + k];
                float a = __half2float(bufA[k]);
                float2 th = tanh2_f16(a + c4.x, a + c4.y);
                m0 = fmaf(c4.z, th.x, m0);
                m1 = fmaf(c4.z, th.y, m1);
            }
            if (u0 + 2 * STRIP < UDIM) {
                #pragma unroll
                for (int k = 0; k < STRIP; k++)
                    bufA[k] = __ldg(ae + (size_t)(u0 + 2 * STRIP + k) * ENL);
            }
            #pragma unroll
            for (int k = 0; k < STRIP; k++) {
                float4 c4 = css[half][u0 + STRIP + k];
                float a = __half2float(bufB[k]);
                float2 th = tanh2_f16(a + c4.x, a + c4.y);
                m0 = fmaf(c4.z, th.x, m0);
                m1 = fmaf(c4.z, th.y, m1);
            }
        }
    }

    const int widl = t >> 5, lane = t & 31;

    // Per-half max over i
    float2 r = make_float2(m0, m1);
    #pragma unroll
    for (int o = 16; o; o >>= 1) {
        r.x = fmaxf(r.x, __shfl_xor_sync(0xffffffffu, r.x, o));
        r.y = fmaxf(r.y, __shfl_xor_sync(0xffffffffu, r.y, o));
    }
    if (lane == 0) red2[half][widl] = r;
    __syncthreads();
    float2 M = red2[half][0];
    #pragma unroll
    for (int w = 1; w < 16; w++) {
        float2 q = red2[half][w];
        M.x = fmaxf(M.x, q.x); M.y = fmaxf(M.y, q.y);
    }
    __syncthreads();

    float e0 = __expf(m0 - M.x);
    float e1 = __expf(m1 - M.y);

    // Per-half sum over i
    float2 s = make_float2(e0, e1);
    #pragma unroll
    for (int o = 16; o; o >>= 1) {
        s.x += __shfl_xor_sync(0xffffffffu, s.x, o);
        s.y += __shfl_xor_sync(0xffffffffu, s.y, o);
    }
    if (lane == 0) red2[half][widl] = s;
    __syncthreads();
    float2 S = red2[half][0];
    #pragma unroll
    for (int w = 1; w < 16; w++) {
        float2 q = red2[half][w];
        S.x += q.x; S.y += q.y;
    }

    float a0 = e0 / S.x, a1 = e1 / S.y;
    alph[half][t] = make_float2(a0, a1);

    // Output layout (flat tuple): [output | alphas | p_gen]
    float* alphas_out = out + BSZ * DEL * ENL;
    float* pgen_out   = out + 2 * BSZ * DEL * ENL;
    const int base = ((b * DEL + j0 + 2 * half) * ENL) + t;
    alphas_out[base      ] = a0;
    alphas_out[base + ENL] = a1;
    pgen_out[base      ] = 1.f / (1.f + __expf(-m0));
    pgen_out[base + ENL] = 1.f / (1.f + __expf(-m1));
    __syncthreads();

    // Phase 2: sum_en[j][e=t] = sum_i alphas[j][i] * en[b][i][e], pipelined.
    float s0 = 0.f, s1 = 0.f;
    const float* enb = en + (size_t)b * ENL * EDIM + t;
    {
        float bufA[STRIP], bufB[STRIP];
        #pragma unroll
        for (int k = 0; k < STRIP; k++)
            bufA[k] = __ldg(enb + (size_t)k * EDIM);

        #pragma unroll 1
        for (int i0 = 0; i0 < ENL; i0 += 2 * STRIP) {
            #pragma unroll
            for (int k = 0; k < STRIP; k++)
                bufB[k] = __ldg(enb + (size_t)(i0 + STRIP + k) * EDIM);
            #pragma unroll
            for (int k = 0; k < STRIP; k++) {
                float2 av = alph[half][i0 + k];
                s0 = fmaf(av.x, bufA[k], s0);
                s1 = fmaf(av.y, bufA[k], s1);
            }
            if (i0 + 2 * STRIP < ENL) {
                #pragma unroll
                for (int k = 0; k < STRIP; k++)
                    bufA[k] = __ldg(enb + (size_t)(i0 + 2 * STRIP + k) * EDIM);
            }
            #pragma unroll
            for (int k = 0; k < STRIP; k++) {
                float2 av = alph[half][i0 + STRIP + k];
                s0 = fmaf(av.x, bufB[k], s0);
                s1 = fmaf(av.y, bufB[k], s1);
            }
        }
    }
    const int ob = ((b * DEL + j0 + 2 * half) * EDIM) + t;
    out[ob       ] = de[ob       ] + s0;
    out[ob + EDIM] = de[ob + EDIM] + s1;
}

// ---------------------------------------------------------------------------
extern "C" void kernel_launch(void* const* d_in, const int* in_sizes, int n_in,
                              void* d_out, int out_size)
{
    const float* en     = (const float*)d_in[0];
    const float* de     = (const float*)d_in[1];
    const float* topics = (const float*)d_in[2];
    const float* w_en   = (const float*)d_in[3];
    const float* w_de   = (const float*)d_in[4];
    const float* nu     = (const float*)d_in[5];
    const float* wt     = (const float*)d_in[6];
    float* out = (float*)d_out;

    k_gemm_aeT<<<dim3(ENL / 64, UDIM / 128, BSZ), 256>>>(en, w_en);
    k_c<<<dim3(UDIM / 64, BSZ), 256>>>(de, w_de, topics, wt);
    k_attn<<<dim3(DEL / 4, BSZ), 1024>>>(en, de, nu, out);
}

// round 12
// speedup vs baseline: 1.0021x; 1.0021x over previous
#include <cuda_runtime.h>
#include <cuda_fp16.h>

// Problem shapes (fixed by the dataset)
#define BSZ  8
#define ENL  512   // encoder length
#define DEL  64    // decoder length
#define EDIM 512   // embedding
#define UDIM 512   // units
#define TDIM 100   // topics
#define STRIP 8    // strip depth in fused kernel

// Scratch (no cudaMalloc allowed)
__device__ __half g_aeT[BSZ * UDIM * ENL];  // att_en transposed: [b][u][i] (fp16, 4 MB)
__device__ float  g_c  [BSZ * DEL * UDIM];  // att_de + topic bias: [b][j][u] (1 MB)

typedef unsigned long long ull;

__device__ __forceinline__ ull pack2(float x, float y) {
    ull r; asm("mov.b64 %0, {%1, %2};" : "=l"(r) : "f"(x), "f"(y)); return r;
}
__device__ __forceinline__ void unpack2(ull p, float& x, float& y) {
    asm("mov.b64 {%0, %1}, %2;" : "=f"(x), "=f"(y) : "l"(p));
}
__device__ __forceinline__ ull fma2(ull a, ull b, ull c) {
    ull d; asm("fma.rn.f32x2 %0, %1, %2, %3;" : "=l"(d) : "l"(a), "l"(b), "l"(c));
    return d;
}
__device__ __forceinline__ unsigned cvt_f16x2(float lo, float hi) {
    unsigned p;
    asm("cvt.rn.f16x2.f32 %0, %1, %2;" : "=r"(p) : "f"(hi), "f"(lo));
    return p;
}
__device__ __forceinline__ __half2 htanh2(__half2 x) {
    unsigned xi = *reinterpret_cast<unsigned*>(&x), r;
    asm("tanh.approx.f16x2 %0, %1;" : "=r"(r) : "r"(xi));
    return *reinterpret_cast<__half2*>(&r);
}

// ---------------------------------------------------------------------------
// Kernel 1: g_aeT[b][u][i] = (half) sum_e en[b][i][e] * w_en[e][u]
// (unchanged from R11 — measured 50.6us)
// ---------------------------------------------------------------------------
__global__ void __launch_bounds__(256, 2) k_gemm_aeT(
    const float* __restrict__ en, const float* __restrict__ w_en)
{
    const int b  = blockIdx.z;
    const int u0 = blockIdx.y * 128;
    const int i0 = blockIdx.x * 64;

    __shared__ float As[2][16][128];  // [e][u]
    __shared__ float Bs[2][16][68];   // [e][i] (padded)

    const int tid = threadIdx.x;
    const int tx = tid & 15;
    const int ty = tid >> 4;

    const int ua = tid & 127;
    const int ea = tid >> 7;
    const int eb = tid & 15;
    const int ib = tid >> 4;

    const float* pa = w_en + (size_t)ea * UDIM + u0 + ua;
    const float* pb = en + (size_t)b * ENL * EDIM + (size_t)(i0 + ib) * EDIM + eb;

    ull acc[4][4] = {};   // [u-pair][i]

    #pragma unroll
    for (int p = 0; p < 8; p++)
        As[0][ea + 2 * p][ua] = pa[(size_t)(2 * p) * UDIM];
    #pragma unroll
    for (int p = 0; p < 4; p++)
        Bs[0][eb][ib + 16 * p] = pb[(size_t)(16 * p) * EDIM];
    __syncthreads();

    int s = 0;
    for (int t = 0; t < 32; t++) {
        float ra[8], rb[4];
        if (t < 31) {
            const float* qa = pa + (size_t)(t + 1) * 16 * UDIM;
            const float* qb = pb + (t + 1) * 16;
            #pragma unroll
            for (int p = 0; p < 8; p++) ra[p] = qa[(size_t)(2 * p) * UDIM];
            #pragma unroll
            for (int p = 0; p < 4; p++) rb[p] = qb[(size_t)(16 * p) * EDIM];
        }
        #pragma unroll
        for (int k = 0; k < 16; k++) {
            const ulonglong2 A03 = *(const ulonglong2*)&As[s][k][ty * 8];
            const ulonglong2 A47 = *(const ulonglong2*)&As[s][k][ty * 8 + 4];
            const float4 bv = *(const float4*)&Bs[s][k][tx * 4];
            const ull b0 = pack2(bv.x, bv.x), b1 = pack2(bv.y, bv.y);
            const ull b2 = pack2(bv.z, bv.z), b3 = pack2(bv.w, bv.w);
            acc[0][0]=fma2(A03.x,b0,acc[0][0]); acc[0][1]=fma2(A03.x,b1,acc[0][1]);
            acc[0][2]=fma2(A03.x,b2,acc[0][2]); acc[0][3]=fma2(A03.x,b3,acc[0][3]);
            acc[1][0]=fma2(A03.y,b0,acc[1][0]); acc[1][1]=fma2(A03.y,b1,acc[1][1]);
            acc[1][2]=fma2(A03.y,b2,acc[1][2]); acc[1][3]=fma2(A03.y,b3,acc[1][3]);
            acc[2][0]=fma2(A47.x,b0,acc[2][0]); acc[2][1]=fma2(A47.x,b1,acc[2][1]);
            acc[2][2]=fma2(A47.x,b2,acc[2][2]); acc[2][3]=fma2(A47.x,b3,acc[2][3]);
            acc[3][0]=fma2(A47.y,b0,acc[3][0]); acc[3][1]=fma2(A47.y,b1,acc[3][1]);
            acc[3][2]=fma2(A47.y,b2,acc[3][2]); acc[3][3]=fma2(A47.y,b3,acc[3][3]);
        }
        if (t < 31) {
            #pragma unroll
            for (int p = 0; p < 8; p++) As[s ^ 1][ea + 2 * p][ua] = ra[p];
            #pragma unroll
            for (int p = 0; p < 4; p++) Bs[s ^ 1][eb][ib + 16 * p] = rb[p];
        }
        __syncthreads();
        s ^= 1;
    }

    float f[8][4];
    #pragma unroll
    for (int up = 0; up < 4; up++)
        #pragma unroll
        for (int i = 0; i < 4; i++)
            unpack2(acc[up][i], f[2 * up][i], f[2 * up + 1][i]);

    __half* outp = g_aeT + (size_t)b * UDIM * ENL
                 + (size_t)(u0 + ty * 8) * ENL + i0 + tx * 4;
    #pragma unroll
    for (int q = 0; q < 8; q++) {
        uint2 hv = make_uint2(cvt_f16x2(f[q][0], f[q][1]),
                              cvt_f16x2(f[q][2], f[q][3]));
        *(uint2*)(outp + (size_t)q * ENL) = hv;
    }
}

// ---------------------------------------------------------------------------
// Kernel 2: g_c[b][j][u] = sum_e de[b][j][e] * w_de[e][u] + tw[b][u]
// (unchanged)
// ---------------------------------------------------------------------------
__global__ void __launch_bounds__(256) k_c(
    const float* __restrict__ de, const float* __restrict__ w_de,
    const float* __restrict__ topics, const float* __restrict__ wt)
{
    const int b  = blockIdx.y;
    const int u0 = blockIdx.x * 64;
    __shared__ float As[16][68];
    __shared__ float Bs[16][68];
    __shared__ float tws[64];
    const float* deb = de + (size_t)b * DEL * EDIM;
    const int tid = threadIdx.x;
    const int tj = tid & 15;
    const int tu = tid >> 4;
    ull acc2[4][2] = {};

    if (tid < 64) {
        float acc = 0.f;
        const float* wr = wt + (size_t)(u0 + tid) * TDIM;
        const float* tp = topics + b * TDIM;
        #pragma unroll 4
        for (int t = 0; t < TDIM; t++) acc = fmaf(tp[t], wr[t], acc);
        tws[tid] = acc;
    }

    for (int e0 = 0; e0 < EDIM; e0 += 16) {
        #pragma unroll
        for (int r = 0; r < 4; r++) {
            int l = tid + 256 * r;
            int e = l & 15, j = l >> 4;
            As[e][j] = deb[(size_t)j * EDIM + e0 + e];
        }
        #pragma unroll
        for (int r = 0; r < 4; r++) {
            int l = tid + 256 * r;
            int e = l >> 6, uu = l & 63;
            Bs[e][uu] = w_de[(size_t)(e0 + e) * UDIM + u0 + uu];
        }
        __syncthreads();
        #pragma unroll
        for (int k = 0; k < 16; k++) {
            const float4 av = *(const float4*)&As[k][tj * 4];
            const ull b01 = *(const ull*)&Bs[k][tu * 4];
            const ull b23 = *(const ull*)&Bs[k][tu * 4 + 2];
            ull pa0 = pack2(av.x, av.x), pa1 = pack2(av.y, av.y);
            ull pa2 = pack2(av.z, av.z), pa3 = pack2(av.w, av.w);
            acc2[0][0] = fma2(pa0, b01, acc2[0][0]); acc2[0][1] = fma2(pa0, b23, acc2[0][1]);
            acc2[1][0] = fma2(pa1, b01, acc2[1][0]); acc2[1][1] = fma2(pa1, b23, acc2[1][1]);
            acc2[2][0] = fma2(pa2, b01, acc2[2][0]); acc2[2][1] = fma2(pa2, b23, acc2[2][1]);
            acc2[3][0] = fma2(pa3, b01, acc2[3][0]); acc2[3][1] = fma2(pa3, b23, acc2[3][1]);
        }
        __syncthreads();
    }
    #pragma unroll
    for (int r = 0; r < 4; r++) {
        float2 v01, v23;
        unpack2(acc2[r][0], v01.x, v01.y);
        unpack2(acc2[r][1], v23.x, v23.y);
        int j = tj * 4 + r;
        float* row = g_c + ((size_t)b * DEL + j) * UDIM + u0 + tu * 4;
        row[0] = v01.x + tws[tu * 4 + 0];
        row[1] = v01.y + tws[tu * 4 + 1];
        row[2] = v23.x + tws[tu * 4 + 2];
        row[3] = v23.y + tws[tu * 4 + 3];
    }
}

// ---------------------------------------------------------------------------
// Kernel 3 (fused attention): block = (b, j0..j0+3), 1024 threads.
// Phase 1: 4 quarters of 256 threads; quarter q owns j=j0+q; each thread
// handles 2 encoder positions via one half2 load. Inner loop per u:
// LDS.64 {c-splat half2, nu} + HADD2 + tanh2 + 2 cvt + 2 FFMA (8 instrs/2 pairs).
// No softmax max-pass (|mu| <= sum|nu| ~ 20, exp safe in fp32).
// Phase 2: half-based mapping (unchanged from R10/R11).
// ---------------------------------------------------------------------------
__global__ void __launch_bounds__(1024, 1) k_attn(
    const float* __restrict__ en, const float* __restrict__ de,
    const float* __restrict__ nu, float* __restrict__ out)
{
    const int b   = blockIdx.y;
    const int j0  = blockIdx.x * 4;
    const int tid = threadIdx.x;
    const int q   = tid >> 8;          // quarter 0..3 -> j = j0+q
    const int tq  = tid & 255;         // thread within quarter

    __shared__ uint2 css[4][UDIM];     // [q][u] = { half2(c,c), fp32 nu bits }
    __shared__ float alph_s[ENL][4];   // [i][q]
    __shared__ float redq[4][8];

    // Fill css for this quarter's j (c pre-splatted to half2; nu fp32)
    {
        const float* cb = g_c + ((size_t)b * DEL + j0 + q) * UDIM;
        #pragma unroll
        for (int uu = tq; uu < UDIM; uu += 256) {
            float cv = cb[uu];
            __half2 ch = __float2half2_rn(cv);
            css[q][uu] = make_uint2(*reinterpret_cast<unsigned*>(&ch),
                                    __float_as_uint(nu[uu]));
        }
    }
    __syncthreads();

    // Phase 1: mu for i = 2tq, 2tq+1 and j = j0+q. Pipelined half2 strips.
    const __half2* ae = reinterpret_cast<const __half2*>(
                            g_aeT + (size_t)b * UDIM * ENL) + tq;
    float m0 = 0.f, m1 = 0.f;
    {
        __half2 bufA[STRIP], bufB[STRIP];
        #pragma unroll
        for (int k = 0; k < STRIP; k++)
            bufA[k] = __ldg(ae + (size_t)k * (ENL / 2));

        #pragma unroll 1
        for (int u0 = 0; u0 < UDIM; u0 += 2 * STRIP) {
            #pragma unroll
            for (int k = 0; k < STRIP; k++)
                bufB[k] = __ldg(ae + (size_t)(u0 + STRIP + k) * (ENL / 2));
            #pragma unroll
            for (int k = 0; k < STRIP; k++) {
                uint2 cn = css[q][u0 + k];
                __half2 ch = *reinterpret_cast<__half2*>(&cn.x);
                float nv = __uint_as_float(cn.y);
                float2 tf = __half22float2(htanh2(__hadd2(bufA[k], ch)));
                m0 = fmaf(nv, tf.x, m0);
                m1 = fmaf(nv, tf.y, m1);
            }
            if (u0 + 2 * STRIP < UDIM) {
                #pragma unroll
                for (int k = 0; k < STRIP; k++)
                    bufA[k] = __ldg(ae + (size_t)(u0 + 2 * STRIP + k) * (ENL / 2));
            }
            #pragma unroll
            for (int k = 0; k < STRIP; k++) {
                uint2 cn = css[q][u0 + STRIP + k];
                __half2 ch = *reinterpret_cast<__half2*>(&cn.x);
                float nv = __uint_as_float(cn.y);
                float2 tf = __half22float2(htanh2(__hadd2(bufB[k], ch)));
                m0 = fmaf(nv, tf.x, m0);
                m1 = fmaf(nv, tf.y, m1);
            }
        }
    }

    // Softmax without max-subtraction (numerically safe: |mu| <= ~20).
    float e0 = __expf(m0);
    float e1 = __expf(m1);

    // Sum over i within quarter: warp reduce, then 8 warps via smem.
    const int widq = tq >> 5, lane = tq & 31;
    float sum = e0 + e1;
    #pragma unroll
    for (int o = 16; o; o >>= 1)
        sum += __shfl_xor_sync(0xffffffffu, sum, o);
    if (lane == 0) redq[q][widq] = sum;
    __syncthreads();
    float S = redq[q][0];
    #pragma unroll
    for (int w = 1; w < 8; w++) S += redq[q][w];

    float inv = 1.f / S;
    float a0 = e0 * inv, a1 = e1 * inv;
    alph_s[2 * tq][q]     = a0;
    alph_s[2 * tq + 1][q] = a1;

    // Outputs for this quarter's j: alphas + p_gen (float2 contiguous stores)
    float* alphas_out = out + BSZ * DEL * ENL;
    float* pgen_out   = out + 2 * BSZ * DEL * ENL;
    const int base = ((b * DEL + j0 + q) * ENL) + 2 * tq;
    *(float2*)(alphas_out + base) = make_float2(a0, a1);
    *(float2*)(pgen_out + base) =
        make_float2(1.f / (1.f + __expf(-m0)), 1.f / (1.f + __expf(-m1)));
    __syncthreads();

    // Phase 2: half-based mapping. half h owns j-pair (j0+2h, j0+2h+1), e = t.
    const int half = tid >> 9;
    const int t    = tid & 511;
    float s0 = 0.f, s1 = 0.f;
    const float* enb = en + (size_t)b * ENL * EDIM + t;
    {
        float bufA[STRIP], bufB[STRIP];
        #pragma unroll
        for (int k = 0; k < STRIP; k++)
            bufA[k] = __ldg(enb + (size_t)k * EDIM);

        #pragma unroll 1
        for (int i0 = 0; i0 < ENL; i0 += 2 * STRIP) {
            #pragma unroll
            for (int k = 0; k < STRIP; k++)
                bufB[k] = __ldg(enb + (size_t)(i0 + STRIP + k) * EDIM);
            #pragma unroll
            for (int k = 0; k < STRIP; k++) {
                float2 av = *(const float2*)&alph_s[i0 + k][2 * half];
                s0 = fmaf(av.x, bufA[k], s0);
                s1 = fmaf(av.y, bufA[k], s1);
            }
            if (i0 + 2 * STRIP < ENL) {
                #pragma unroll
                for (int k = 0; k < STRIP; k++)
                    bufA[k] = __ldg(enb + (size_t)(i0 + 2 * STRIP + k) * EDIM);
            }
            #pragma unroll
            for (int k = 0; k < STRIP; k++) {
                float2 av = *(const float2*)&alph_s[i0 + STRIP + k][2 * half];
                s0 = fmaf(av.x, bufB[k], s0);
                s1 = fmaf(av.y, bufB[k], s1);
            }
        }
    }
    const int ob = ((b * DEL + j0 + 2 * half) * EDIM) + t;
    out[ob       ] = de[ob       ] + s0;
    out[ob + EDIM] = de[ob + EDIM] + s1;
}

// ---------------------------------------------------------------------------
extern "C" void kernel_launch(void* const* d_in, const int* in_sizes, int n_in,
                              void* d_out, int out_size)
{
    const float* en     = (const float*)d_in[0];
    const float* de     = (const float*)d_in[1];
    const float* topics = (const float*)d_in[2];
    const float* w_en   = (const float*)d_in[3];
    const float* w_de   = (const float*)d_in[4];
    const float* nu     = (const float*)d_in[5];
    const float* wt     = (const float*)d_in[6];
    float* out = (float*)d_out;

    k_gemm_aeT<<<dim3(ENL / 64, UDIM / 128, BSZ), 256>>>(en, w_en);
    k_c<<<dim3(UDIM / 64, BSZ), 256>>>(de, w_de, topics, wt);
    k_attn<<<dim3(DEL / 4, BSZ), 1024>>>(en, de, nu, out);
}

// round 13
// speedup vs baseline: 1.2103x; 1.2077x over previous
#include <cuda_runtime.h>
#include <cuda_fp16.h>

// Problem shapes (fixed by the dataset)
#define BSZ  8
#define ENL  512   // encoder length
#define DEL  64    // decoder length
#define EDIM 512   // embedding
#define UDIM 512   // units
#define TDIM 100   // topics
#define STRIP 8    // strip depth in fused kernel

// Scratch (no cudaMalloc allowed)
__device__ __half g_aeT[BSZ * UDIM * ENL];  // att_en transposed: [b][u][i] (fp16, 4 MB)
__device__ float  g_c  [BSZ * DEL * UDIM];  // att_de + topic bias: [b][j][u] (1 MB)

typedef unsigned long long ull;

__device__ __forceinline__ ull pack2(float x, float y) {
    ull r; asm("mov.b64 %0, {%1, %2};" : "=l"(r) : "f"(x), "f"(y)); return r;
}
__device__ __forceinline__ void unpack2(ull p, float& x, float& y) {
    asm("mov.b64 {%0, %1}, %2;" : "=f"(x), "=f"(y) : "l"(p));
}
__device__ __forceinline__ ull fma2(ull a, ull b, ull c) {
    ull d; asm("fma.rn.f32x2 %0, %1, %2, %3;" : "=l"(d) : "l"(a), "l"(b), "l"(c));
    return d;
}
__device__ __forceinline__ unsigned cvt_f16x2(float lo, float hi) {
    unsigned p;
    asm("cvt.rn.f16x2.f32 %0, %1, %2;" : "=r"(p) : "f"(hi), "f"(lo));
    return p;
}
__device__ __forceinline__ __half2 htanh2(__half2 x) {
    unsigned xi = *reinterpret_cast<unsigned*>(&x), r;
    asm("tanh.approx.f16x2 %0, %1;" : "=r"(r) : "r"(xi));
    return *reinterpret_cast<__half2*>(&r);
}
__device__ __forceinline__ unsigned f2tf(float f) {
    unsigned r;
    asm("cvt.rna.tf32.f32 %0, %1;" : "=r"(r) : "f"(f));
    return r;
}
__device__ __forceinline__ void mma_tf32(
    float& c0, float& c1, float& c2, float& c3,
    unsigned a0, unsigned a1, unsigned a2, unsigned a3,
    unsigned b0, unsigned b1)
{
    asm volatile(
        "mma.sync.aligned.m16n8k8.row.col.f32.tf32.tf32.f32 "
        "{%0,%1,%2,%3}, {%4,%5,%6,%7}, {%8,%9}, {%0,%1,%2,%3};"
        : "+f"(c0), "+f"(c1), "+f"(c2), "+f"(c3)
        : "r"(a0), "r"(a1), "r"(a2), "r"(a3), "r"(b0), "r"(b1));
}

// ---------------------------------------------------------------------------
// Kernel 1 (TENSOR CORES, tf32): g_aeT[b][u][i] = (half) sum_e en[b][i][e]*w_en[e][u]
// C = A x B with A[u][e] = w_en[e][u] (row-major M=u, K=e via indexed reads of
// natural As[e][u]) and B[e][i] = en[i][e] (col-major K=e, N=i via natural Bs[i][e]).
// Block: 128u x 64i, BK=16, 256 thr = 8 warps (4 wu x 2 wi), warp tile 32x32.
// Double-buffered smem, tf32 conversion at staging.
// ---------------------------------------------------------------------------
__global__ void __launch_bounds__(256, 2) k_gemm_aeT(
    const float* __restrict__ en, const float* __restrict__ w_en)
{
    const int b  = blockIdx.z;
    const int u0 = blockIdx.y * 128;
    const int i0 = blockIdx.x * 64;

    __shared__ unsigned As[2][16][136];  // [e][u] tf32, pad 136 -> banks (8e+u)%32
    __shared__ unsigned Bs[2][64][20];   // [i][e] tf32, pad 20  -> banks (20i+e)%32

    const int tid  = threadIdx.x;
    const int lane = tid & 31;
    const int warp = tid >> 5;
    const int wu = warp & 3;       // u subtile (32 each)
    const int wi = warp >> 2;      // i subtile (32 each)

    // A staging map: float4 per pass; u4 = (tid%32)*4, e = tid/32 (+8 pass 2)
    const int au4 = (tid & 31) * 4;
    const int ae_ = tid >> 5;
    // B staging map: float4; i = tid/4, e4 = (tid%4)*4
    const int bi  = tid >> 2;
    const int be4 = (tid & 3) * 4;

    const float* pa = w_en + (size_t)ae_ * UDIM + u0 + au4;
    const float* pb = en + ((size_t)b * ENL + i0 + bi) * EDIM + be4;

    float c[2][4][4];
    #pragma unroll
    for (int mf = 0; mf < 2; mf++)
        #pragma unroll
        for (int nf = 0; nf < 4; nf++)
            #pragma unroll
            for (int r = 0; r < 4; r++) c[mf][nf][r] = 0.f;

    // Prologue: stage tile 0
    #pragma unroll
    for (int p = 0; p < 2; p++) {
        float4 v = *(const float4*)(pa + (size_t)(8 * p) * UDIM);
        uint4 w = make_uint4(f2tf(v.x), f2tf(v.y), f2tf(v.z), f2tf(v.w));
        *(uint4*)&As[0][ae_ + 8 * p][au4] = w;
    }
    {
        float4 v = *(const float4*)pb;
        uint4 w = make_uint4(f2tf(v.x), f2tf(v.y), f2tf(v.z), f2tf(v.w));
        *(uint4*)&Bs[0][bi][be4] = w;
    }
    __syncthreads();

    int s = 0;
    for (int t = 0; t < 32; t++) {
        float4 ra[2], rb;
        if (t < 31) {
            const float* qa = pa + (size_t)(t + 1) * 16 * UDIM;
            const float* qb = pb + (t + 1) * 16;
            #pragma unroll
            for (int p = 0; p < 2; p++)
                ra[p] = *(const float4*)(qa + (size_t)(8 * p) * UDIM);
            rb = *(const float4*)qb;
        }

        #pragma unroll
        for (int k8 = 0; k8 < 2; k8++) {
            const int eb = k8 * 8;
            const int e0 = eb + (lane & 3);
            const int rA = wu * 32 + (lane >> 2);
            unsigned a[2][4];
            #pragma unroll
            for (int mf = 0; mf < 2; mf++) {
                int row = rA + mf * 16;
                a[mf][0] = As[s][e0    ][row    ];
                a[mf][1] = As[s][e0    ][row + 8];
                a[mf][2] = As[s][e0 + 4][row    ];
                a[mf][3] = As[s][e0 + 4][row + 8];
            }
            unsigned bfr[4][2];
            const int cI = wi * 32 + (lane >> 2);
            #pragma unroll
            for (int nf = 0; nf < 4; nf++) {
                int col = cI + nf * 8;
                bfr[nf][0] = Bs[s][col][e0    ];
                bfr[nf][1] = Bs[s][col][e0 + 4];
            }
            #pragma unroll
            for (int mf = 0; mf < 2; mf++)
                #pragma unroll
                for (int nf = 0; nf < 4; nf++)
                    mma_tf32(c[mf][nf][0], c[mf][nf][1], c[mf][nf][2], c[mf][nf][3],
                             a[mf][0], a[mf][1], a[mf][2], a[mf][3],
                             bfr[nf][0], bfr[nf][1]);
        }

        if (t < 31) {
            #pragma unroll
            for (int p = 0; p < 2; p++) {
                uint4 w = make_uint4(f2tf(ra[p].x), f2tf(ra[p].y),
                                     f2tf(ra[p].z), f2tf(ra[p].w));
                *(uint4*)&As[s ^ 1][ae_ + 8 * p][au4] = w;
            }
            uint4 w = make_uint4(f2tf(rb.x), f2tf(rb.y), f2tf(rb.z), f2tf(rb.w));
            *(uint4*)&Bs[s ^ 1][bi][be4] = w;
        }
        __syncthreads();
        s ^= 1;
    }

    // Epilogue: C frags -> fp16 aeT[u][i]
    __half* outb = g_aeT + (size_t)b * UDIM * ENL;
    #pragma unroll
    for (int mf = 0; mf < 2; mf++) {
        const int ug = u0 + wu * 32 + mf * 16 + (lane >> 2);
        #pragma unroll
        for (int nf = 0; nf < 4; nf++) {
            const int ig = i0 + wi * 32 + nf * 8 + 2 * (lane & 3);
            *(unsigned*)(outb + (size_t)ug * ENL + ig) =
                cvt_f16x2(c[mf][nf][0], c[mf][nf][1]);
            *(unsigned*)(outb + (size_t)(ug + 8) * ENL + ig) =
                cvt_f16x2(c[mf][nf][2], c[mf][nf][3]);
        }
    }
}

// ---------------------------------------------------------------------------
// Kernel 2: g_c[b][j][u] = sum_e de[b][j][e] * w_de[e][u] + tw[b][u]
// (unchanged from R12)
// ---------------------------------------------------------------------------
__global__ void __launch_bounds__(256) k_c(
    const float* __restrict__ de, const float* __restrict__ w_de,
    const float* __restrict__ topics, const float* __restrict__ wt)
{
    const int b  = blockIdx.y;
    const int u0 = blockIdx.x * 64;
    __shared__ float As[16][68];
    __shared__ float Bs[16][68];
    __shared__ float tws[64];
    const float* deb = de + (size_t)b * DEL * EDIM;
    const int tid = threadIdx.x;
    const int tj = tid & 15;
    const int tu = tid >> 4;
    ull acc2[4][2] = {};

    if (tid < 64) {
        float acc = 0.f;
        const float* wr = wt + (size_t)(u0 + tid) * TDIM;
        const float* tp = topics + b * TDIM;
        #pragma unroll 4
        for (int t = 0; t < TDIM; t++) acc = fmaf(tp[t], wr[t], acc);
        tws[tid] = acc;
    }

    for (int e0 = 0; e0 < EDIM; e0 += 16) {
        #pragma unroll
        for (int r = 0; r < 4; r++) {
            int l = tid + 256 * r;
            int e = l & 15, j = l >> 4;
            As[e][j] = deb[(size_t)j * EDIM + e0 + e];
        }
        #pragma unroll
        for (int r = 0; r < 4; r++) {
            int l = tid + 256 * r;
            int e = l >> 6, uu = l & 63;
            Bs[e][uu] = w_de[(size_t)(e0 + e) * UDIM + u0 + uu];
        }
        __syncthreads();
        #pragma unroll
        for (int k = 0; k < 16; k++) {
            const float4 av = *(const float4*)&As[k][tj * 4];
            const ull b01 = *(const ull*)&Bs[k][tu * 4];
            const ull b23 = *(const ull*)&Bs[k][tu * 4 + 2];
            ull pa0 = pack2(av.x, av.x), pa1 = pack2(av.y, av.y);
            ull pa2 = pack2(av.z, av.z), pa3 = pack2(av.w, av.w);
            acc2[0][0] = fma2(pa0, b01, acc2[0][0]); acc2[0][1] = fma2(pa0, b23, acc2[0][1]);
            acc2[1][0] = fma2(pa1, b01, acc2[1][0]); acc2[1][1] = fma2(pa1, b23, acc2[1][1]);
            acc2[2][0] = fma2(pa2, b01, acc2[2][0]); acc2[2][1] = fma2(pa2, b23, acc2[2][1]);
            acc2[3][0] = fma2(pa3, b01, acc2[3][0]); acc2[3][1] = fma2(pa3, b23, acc2[3][1]);
        }
        __syncthreads();
    }
    #pragma unroll
    for (int r = 0; r < 4; r++) {
        float2 v01, v23;
        unpack2(acc2[r][0], v01.x, v01.y);
        unpack2(acc2[r][1], v23.x, v23.y);
        int j = tj * 4 + r;
        float* row = g_c + ((size_t)b * DEL + j) * UDIM + u0 + tu * 4;
        row[0] = v01.x + tws[tu * 4 + 0];
        row[1] = v01.y + tws[tu * 4 + 1];
        row[2] = v23.x + tws[tu * 4 + 2];
        row[3] = v23.y + tws[tu * 4 + 3];
    }
}

// ---------------------------------------------------------------------------
// Kernel 3 (fused attention): block = (b, j0..j0+3), 1024 threads.
// (unchanged from R12)
// ---------------------------------------------------------------------------
__global__ void __launch_bounds__(1024, 1) k_attn(
    const float* __restrict__ en, const float* __restrict__ de,
    const float* __restrict__ nu, float* __restrict__ out)
{
    const int b   = blockIdx.y;
    const int j0  = blockIdx.x * 4;
    const int tid = threadIdx.x;
    const int q   = tid >> 8;
    const int tq  = tid & 255;

    __shared__ uint2 css[4][UDIM];
    __shared__ float alph_s[ENL][4];
    __shared__ float redq[4][8];

    {
        const float* cb = g_c + ((size_t)b * DEL + j0 + q) * UDIM;
        #pragma unroll
        for (int uu = tq; uu < UDIM; uu += 256) {
            float cv = cb[uu];
            __half2 ch = __float2half2_rn(cv);
            css[q][uu] = make_uint2(*reinterpret_cast<unsigned*>(&ch),
                                    __float_as_uint(nu[uu]));
        }
    }
    __syncthreads();

    const __half2* ae = reinterpret_cast<const __half2*>(
                            g_aeT + (size_t)b * UDIM * ENL) + tq;
    float m0 = 0.f, m1 = 0.f;
    {
        __half2 bufA[STRIP], bufB[STRIP];
        #pragma unroll
        for (int k = 0; k < STRIP; k++)
            bufA[k] = __ldg(ae + (size_t)k * (ENL / 2));

        #pragma unroll 1
        for (int u0 = 0; u0 < UDIM; u0 += 2 * STRIP) {
            #pragma unroll
            for (int k = 0; k < STRIP; k++)
                bufB[k] = __ldg(ae + (size_t)(u0 + STRIP + k) * (ENL / 2));
            #pragma unroll
            for (int k = 0; k < STRIP; k++) {
                uint2 cn = css[q][u0 + k];
                __half2 ch = *reinterpret_cast<__half2*>(&cn.x);
                float nv = __uint_as_float(cn.y);
                float2 tf = __half22float2(htanh2(__hadd2(bufA[k], ch)));
                m0 = fmaf(nv, tf.x, m0);
                m1 = fmaf(nv, tf.y, m1);
            }
            if (u0 + 2 * STRIP < UDIM) {
                #pragma unroll
                for (int k = 0; k < STRIP; k++)
                    bufA[k] = __ldg(ae + (size_t)(u0 + 2 * STRIP + k) * (ENL / 2));
            }
            #pragma unroll
            for (int k = 0; k < STRIP; k++) {
                uint2 cn = css[q][u0 + STRIP + k];
                __half2 ch = *reinterpret_cast<__half2*>(&cn.x);
                float nv = __uint_as_float(cn.y);
                float2 tf = __half22float2(htanh2(__hadd2(bufB[k], ch)));
                m0 = fmaf(nv, tf.x, m0);
                m1 = fmaf(nv, tf.y, m1);
            }
        }
    }

    float e0 = __expf(m0);
    float e1 = __expf(m1);

    const int widq = tq >> 5, lane = tq & 31;
    float sum = e0 + e1;
    #pragma unroll
    for (int o = 16; o; o >>= 1)
        sum += __shfl_xor_sync(0xffffffffu, sum, o);
    if (lane == 0) redq[q][widq] = sum;
    __syncthreads();
    float S = redq[q][0];
    #pragma unroll
    for (int w = 1; w < 8; w++) S += redq[q][w];

    float inv = 1.f / S;
    float a0 = e0 * inv, a1 = e1 * inv;
    alph_s[2 * tq][q]     = a0;
    alph_s[2 * tq + 1][q] = a1;

    float* alphas_out = out + BSZ * DEL * ENL;
    float* pgen_out   = out + 2 * BSZ * DEL * ENL;
    const int base = ((b * DEL + j0 + q) * ENL) + 2 * tq;
    *(float2*)(alphas_out + base) = make_float2(a0, a1);
    *(float2*)(pgen_out + base) =
        make_float2(1.f / (1.f + __expf(-m0)), 1.f / (1.f + __expf(-m1)));
    __syncthreads();

    const int half = tid >> 9;
    const int t    = tid & 511;
    float s0 = 0.f, s1 = 0.f;
    const float* enb = en + (size_t)b * ENL * EDIM + t;
    {
        float bufA[STRIP], bufB[STRIP];
        #pragma unroll
        for (int k = 0; k < STRIP; k++)
            bufA[k] = __ldg(enb + (size_t)k * EDIM);

        #pragma unroll 1
        for (int i0 = 0; i0 < ENL; i0 += 2 * STRIP) {
            #pragma unroll
            for (int k = 0; k < STRIP; k++)
                bufB[k] = __ldg(enb + (size_t)(i0 + STRIP + k) * EDIM);
            #pragma unroll
            for (int k = 0; k < STRIP; k++) {
                float2 av = *(const float2*)&alph_s[i0 + k][2 * half];
                s0 = fmaf(av.x, bufA[k], s0);
                s1 = fmaf(av.y, bufA[k], s1);
            }
            if (i0 + 2 * STRIP < ENL) {
                #pragma unroll
                for (int k = 0; k < STRIP; k++)
                    bufA[k] = __ldg(enb + (size_t)(i0 + 2 * STRIP + k) * EDIM);
            }
            #pragma unroll
            for (int k = 0; k < STRIP; k++) {
                float2 av = *(const float2*)&alph_s[i0 + STRIP + k][2 * half];
                s0 = fmaf(av.x, bufB[k], s0);
                s1 = fmaf(av.y, bufB[k], s1);
            }
        }
    }
    const int ob = ((b * DEL + j0 + 2 * half) * EDIM) + t;
    out[ob       ] = de[ob       ] + s0;
    out[ob + EDIM] = de[ob + EDIM] + s1;
}

// ---------------------------------------------------------------------------
extern "C" void kernel_launch(void* const* d_in, const int* in_sizes, int n_in,
                              void* d_out, int out_size)
{
    const float* en     = (const float*)d_in[0];
    const float* de     = (const float*)d_in[1];
    const float* topics = (const float*)d_in[2];
    const float* w_en   = (const float*)d_in[3];
    const float* w_de   = (const float*)d_in[4];
    const float* nu     = (const float*)d_in[5];
    const float* wt     = (const float*)d_in[6];
    float* out = (float*)d_out;

    k_gemm_aeT<<<dim3(ENL / 64, UDIM / 128, BSZ), 256>>>(en, w_en);
    k_c<<<dim3(UDIM / 64, BSZ), 256>>>(de, w_de, topics, wt);
    k_attn<<<dim3(DEL / 4, BSZ), 1024>>>(en, de, nu, out);
}